// round 4
// baseline (speedup 1.0000x reference)
#include <cuda_runtime.h>
#include <cstdint>

// ChamferDistance: N=4 batches, P1=P2=8192 points, D=3.
// out layout (fp32): [cham_x (4*8192)] [cham_y (4*8192)] [idx_x (4*8192)] [idx_y (4*8192)]
//
// Numerics: reproduce the reference's fp32 rounding sequence exactly:
//   an  = (fl(ax^2) + fl(ay^2)) + fl(az^2)          (rounded MULs + ADDs)
//   ab  = fma(az,bz, fma(ay,by, fl(ax*bx)))         (sequential-k fma chain)
//   d2  = fl( fl(an + bn) - 2*ab )                  (2*ab exact -> fmaf(-2,ab,an+bn))
// argmin tie-break = first index (ascending scan, strict <).
//
// Parallelism: grid = (8 point-blocks) x (4 batches * 2 dirs) x (4 q-chunks)
// = 256 CTAs, 256 threads, 4 queries/thread, 32KB smem -> 2 CTAs/SM, 1 wave.

#define N_B     4
#define P_PTS   8192
#define QS      4
#define QCHUNK  (P_PTS / QS)      // 2048
#define TPB     256
#define PPT     4
#define PTS_BLK (TPB * PPT)       // 1024
#define PB      (P_PTS / PTS_BLK) // 8
#define ND      (N_B * 2)         // 8 (n,dir) combos
#define TOTAL_Q (ND * P_PTS)      // 65536 query slots

// Scratch for per-chunk partial results (device globals: no allocation).
__device__ float g_pdist[QS * TOTAL_Q];
__device__ int   g_pidx [QS * TOTAL_Q];

// ||v||^2 with the reference's rounding: (fl(x^2)+fl(y^2))+fl(z^2)
__device__ __forceinline__ float sqnorm_ref(float x, float y, float z) {
    return __fadd_rn(__fadd_rn(__fmul_rn(x, x), __fmul_rn(y, y)),
                     __fmul_rn(z, z));
}

__global__ __launch_bounds__(TPB, 2)
void chamfer_partial_kernel(const float* __restrict__ x,
                            const float* __restrict__ y)
{
    __shared__ float4 tile[QCHUNK];   // 32 KB: {bx,by,bz,bn}

    const int nd  = blockIdx.y;       // n*2 + dir
    const int n   = nd >> 1;
    const int dir = nd & 1;
    const int qsl = blockIdx.z;       // ref-chunk index
    const int qbase = qsl * QCHUNK;

    const float* qry = dir ? y : x;   // dir0: queries=x refs=y ; dir1: swapped
    const float* ref = dir ? x : y;

    // Stage this ref-chunk into smem with precomputed ||b||^2 (reference rounding).
    {
        const float* rb = ref + ((size_t)n * P_PTS + qbase) * 3;
        for (int i = threadIdx.x; i < QCHUNK; i += TPB) {
            float bx = rb[i * 3 + 0];
            float by = rb[i * 3 + 1];
            float bz = rb[i * 3 + 2];
            tile[i] = make_float4(bx, by, bz, sqnorm_ref(bx, by, bz));
        }
    }

    // This thread's PPT query points: raw coords + an (reference rounding).
    float ax[PPT], ay[PPT], az[PPT], an[PPT];
    const int p0 = blockIdx.x * PTS_BLK + threadIdx.x;
    #pragma unroll
    for (int k = 0; k < PPT; k++) {
        const int p = p0 + k * TPB;
        const float* q = qry + ((size_t)n * P_PTS + p) * 3;
        ax[k] = q[0]; ay[k] = q[1]; az[k] = q[2];
        an[k] = sqnorm_ref(ax[k], ay[k], az[k]);
    }

    __syncthreads();

    float best[PPT];
    int   bidx[PPT];
    #pragma unroll
    for (int k = 0; k < PPT; k++) { best[k] = 3.402823466e38f; bidx[k] = qbase; }

    // Mainloop: 2048 refs x 4 queries/thread. Ascending j + strict '<'
    // == first-argmin within chunk.
    #pragma unroll 4
    for (int j = 0; j < QCHUNK; j++) {
        const float4 b = tile[j];
        const int qidx = qbase + j;
        #pragma unroll
        for (int k = 0; k < PPT; k++) {
            // ab with the reference's (sequential fma) rounding:
            float ab = __fmaf_rn(az[k], b.z,
                        __fmaf_rn(ay[k], b.y,
                         __fmul_rn(ax[k], b.x)));
            // d2 = fl( fl(an+bn) - 2*ab );  2*ab exact -> single fmaf rounding.
            float t  = __fadd_rn(an[k], b.w);
            float d2 = __fmaf_rn(-2.0f, ab, t);
            if (d2 < best[k]) { best[k] = d2; bidx[k] = qidx; }
        }
    }

    #pragma unroll
    for (int k = 0; k < PPT; k++) {
        const int p = p0 + k * TPB;
        const size_t slot = (size_t)qsl * TOTAL_Q + (size_t)nd * P_PTS + p;
        g_pdist[slot] = best[k];
        g_pidx [slot] = bidx[k];
    }
}

__global__ void chamfer_reduce_kernel(float* __restrict__ out)
{
    const int t = blockIdx.x * blockDim.x + threadIdx.x;  // 0..TOTAL_Q-1
    if (t >= TOTAL_Q) return;

    // Ascending chunk order + strict '<' keeps the globally-first argmin.
    float best = g_pdist[t];
    int   bi   = g_pidx[t];
    #pragma unroll
    for (int qsl = 1; qsl < QS; qsl++) {
        float d = g_pdist[(size_t)qsl * TOTAL_Q + t];
        int   i = g_pidx [(size_t)qsl * TOTAL_Q + t];
        if (d < best) { best = d; bi = i; }
    }

    const int nd  = t / P_PTS;
    const int p   = t % P_PTS;
    const int n   = nd >> 1;
    const int dir = nd & 1;

    // out: [cham_x | cham_y | idx_x | idx_y], each N_B*P_PTS floats.
    const int half = N_B * P_PTS;                 // 32768
    const int off  = (dir ? half : 0) + n * P_PTS + p;
    out[off]            = best;
    out[2 * half + off] = (float)bi;
}

extern "C" void kernel_launch(void* const* d_in, const int* in_sizes, int n_in,
                              void* d_out, int out_size)
{
    const float* x = (const float*)d_in[0];   // (4, 8192, 3) fp32
    const float* y = (const float*)d_in[1];   // (4, 8192, 3) fp32
    float* out = (float*)d_out;

    dim3 grid(PB, ND, QS);        // 8 x 8 x 4 = 256 CTAs
    chamfer_partial_kernel<<<grid, TPB>>>(x, y);

    chamfer_reduce_kernel<<<TOTAL_Q / 256, 256>>>(out);
}

// round 5
// speedup vs baseline: 1.1976x; 1.1976x over previous
#include <cuda_runtime.h>
#include <cstdint>

// ChamferDistance: N=4 batches, P1=P2=8192 points, D=3.
// out layout (fp32): [cham_x (4*8192)] [cham_y (4*8192)] [idx_x (4*8192)] [idx_y (4*8192)]
//
// Numerics (reference-exact rounding, proven R4):
//   an  = (fl(ax^2) + fl(ay^2)) + fl(az^2)
//   ab  = fma(az,bz, fma(ay,by, fl(ax*bx)))
//   t   = fl(an + bn)        (emitted as FFMA-imm: fma(bn, 1.0, an) -- bit-identical)
//   d2  = fl(t - 2*ab)       (emitted as FFMA-imm: fma(ab, -2.0, t))
// argmin tie-break = first index (ascending scan, strict <).
//
// Parallelism: grid = 8 point-blocks x 8 (n,dir) x 37 ref-chunks = 2368 CTAs
// = 148 SMs x occ4 x 4 waves EXACTLY (perfect balance; 148=4*37 forces QS=37).
// Ref chunks are uneven (221/222) via computed bounds; ascending order keeps
// the first-argmin semantics across chunks.

#define N_B     4
#define P_PTS   8192
#define QS      37
#define QCH_MAX 222               // ceil(8192/37)
#define TPB     256
#define PPT     4
#define PTS_BLK (TPB * PPT)       // 1024
#define PB      (P_PTS / PTS_BLK) // 8
#define ND      (N_B * 2)         // 8
#define TOTAL_Q (ND * P_PTS)      // 65536

// Scratch for per-chunk partials (device globals: no allocation). ~19.4MB, L2-resident.
__device__ float g_pdist[QS * TOTAL_Q];
__device__ int   g_pidx [QS * TOTAL_Q];

__device__ __forceinline__ float sqnorm_ref(float x, float y, float z) {
    return __fadd_rn(__fadd_rn(__fmul_rn(x, x), __fmul_rn(y, y)),
                     __fmul_rn(z, z));
}

// fl(a+b) emitted as FFMA with immediate multiplier 1.0 (rt_SMSP=1 vs FADD rt=2).
// fma(b*1.0 + a) is bit-identical to a+b (x*1.0 exact, single rounding).
__device__ __forceinline__ float add_via_fma_imm(float a, float b) {
    float r;
    asm("fma.rn.f32 %0, %1, 0f3F800000, %2;" : "=f"(r) : "f"(b), "f"(a));
    return r;
}

__global__ __launch_bounds__(TPB, 4)
void chamfer_partial_kernel(const float* __restrict__ x,
                            const float* __restrict__ y)
{
    __shared__ float4 tile[QCH_MAX];   // 3552 B: {bx,by,bz,bn}

    const int nd  = blockIdx.y;        // n*2 + dir
    const int n   = nd >> 1;
    const int dir = nd & 1;
    const int c   = blockIdx.z;        // ref-chunk 0..36
    const int jStart = (P_PTS * c) / QS;
    const int jEnd   = (P_PTS * (c + 1)) / QS;
    const int cnt    = jEnd - jStart;  // 221 or 222

    const float* qry = dir ? y : x;    // dir0: queries=x refs=y ; dir1: swapped
    const float* ref = dir ? x : y;

    // Stage this ref-chunk into smem with precomputed ||b||^2 (reference rounding).
    {
        const float* rb = ref + ((size_t)n * P_PTS + jStart) * 3;
        for (int i = threadIdx.x; i < cnt; i += TPB) {
            float bx = rb[i * 3 + 0];
            float by = rb[i * 3 + 1];
            float bz = rb[i * 3 + 2];
            tile[i] = make_float4(bx, by, bz, sqnorm_ref(bx, by, bz));
        }
    }

    // This thread's PPT query points: raw coords + an (reference rounding).
    float ax[PPT], ay[PPT], az[PPT], an[PPT];
    const int p0 = blockIdx.x * PTS_BLK + threadIdx.x;
    #pragma unroll
    for (int k = 0; k < PPT; k++) {
        const int p = p0 + k * TPB;
        const float* q = qry + ((size_t)n * P_PTS + p) * 3;
        ax[k] = q[0]; ay[k] = q[1]; az[k] = q[2];
        an[k] = sqnorm_ref(ax[k], ay[k], az[k]);
    }

    __syncthreads();

    float best[PPT];
    int   bidx[PPT];
    #pragma unroll
    for (int k = 0; k < PPT; k++) { best[k] = 3.402823466e38f; bidx[k] = jStart; }

    // Mainloop: ~222 refs x 4 queries/thread. Ascending j + strict '<'
    // == first-argmin within chunk.
    #pragma unroll 4
    for (int j = 0; j < cnt; j++) {
        const float4 b = tile[j];
        const int qidx = jStart + j;
        #pragma unroll
        for (int k = 0; k < PPT; k++) {
            float ab = __fmaf_rn(az[k], b.z,
                        __fmaf_rn(ay[k], b.y,
                         __fmul_rn(ax[k], b.x)));
            float t  = add_via_fma_imm(an[k], b.w);     // fl(an+bn), FFMA-imm
            float d2 = __fmaf_rn(-2.0f, ab, t);         // FFMA-imm (-2 literal)
            if (d2 < best[k]) { best[k] = d2; bidx[k] = qidx; }
        }
    }

    #pragma unroll
    for (int k = 0; k < PPT; k++) {
        const int p = p0 + k * TPB;
        const size_t slot = (size_t)c * TOTAL_Q + (size_t)nd * P_PTS + p;
        g_pdist[slot] = best[k];
        g_pidx [slot] = bidx[k];
    }
}

__global__ void chamfer_reduce_kernel(float* __restrict__ out)
{
    const int t = blockIdx.x * blockDim.x + threadIdx.x;  // 0..TOTAL_Q-1
    if (t >= TOTAL_Q) return;

    // Ascending chunk order + strict '<' keeps the globally-first argmin.
    float best = g_pdist[t];
    int   bi   = g_pidx[t];
    #pragma unroll 4
    for (int c = 1; c < QS; c++) {
        float d = g_pdist[(size_t)c * TOTAL_Q + t];
        int   i = g_pidx [(size_t)c * TOTAL_Q + t];
        if (d < best) { best = d; bi = i; }
    }

    const int nd  = t / P_PTS;
    const int p   = t % P_PTS;
    const int n   = nd >> 1;
    const int dir = nd & 1;

    // out: [cham_x | cham_y | idx_x | idx_y], each N_B*P_PTS floats.
    const int half = N_B * P_PTS;                 // 32768
    const int off  = (dir ? half : 0) + n * P_PTS + p;
    out[off]            = best;
    out[2 * half + off] = (float)bi;
}

extern "C" void kernel_launch(void* const* d_in, const int* in_sizes, int n_in,
                              void* d_out, int out_size)
{
    const float* x = (const float*)d_in[0];   // (4, 8192, 3) fp32
    const float* y = (const float*)d_in[1];   // (4, 8192, 3) fp32
    float* out = (float*)d_out;

    dim3 grid(PB, ND, QS);        // 8 x 8 x 37 = 2368 CTAs = 148*4 * 4 waves
    chamfer_partial_kernel<<<grid, TPB>>>(x, y);

    chamfer_reduce_kernel<<<TOTAL_Q / 256, 256>>>(out);
}